// round 5
// baseline (speedup 1.0000x reference)
#include <cuda_runtime.h>
#include <cstdint>

// ---------------------------------------------------------------------------
// out = scale * signGEMM,  scale = 2^rint(clip(shift,-8,0))
// x [4,2048,4096] -> M=8192, K=4096 ; weight [16384,4096] -> N=16384
// Signs packed as int8 +/-1; IMMA (mma.sync m16n8k32 s8.s8.s32) is exact.
// ---------------------------------------------------------------------------
constexpr int K_DIM = 4096;
constexpr int M_DIM = 8192;
constexpr int N_DIM = 16384;

constexpr int BM = 128;
constexpr int BN = 256;
constexpr int BK = 64;                  // bytes (int8 K-elems) per chunk
constexpr int NKC = K_DIM / BK;         // 64
constexpr int STAGES = 4;
constexpr int A_ST = BM * BK;           // 8192
constexpr int B_ST = BN * BK;           // 16384
constexpr int ST   = A_ST + B_ST;       // 24576
constexpr int SMEM_TOTAL = STAGES * ST; // 98304

__device__ __align__(1024) signed char g_A[(size_t)M_DIM * K_DIM]; // 32 MB
__device__ __align__(1024) signed char g_B[(size_t)N_DIM * K_DIM]; // 64 MB

// ---------------------------------------------------------------------------
// Pack kernels: sign -> int8 +/-1, row-major.
// ---------------------------------------------------------------------------
__device__ __forceinline__ uint32_t sign4_s8(float4 v) {
    uint32_t w;
    w  = (v.x >= 0.0f ? 0x01u : 0xFFu);
    w |= (v.y >= 0.0f ? 0x01u : 0xFFu) << 8;
    w |= (v.z >= 0.0f ? 0x01u : 0xFFu) << 16;
    w |= (v.w >= 0.0f ? 0x01u : 0xFFu) << 24;
    return w;
}

__global__ void __launch_bounds__(256) pack_x_kernel(const float* __restrict__ x) {
    const int m = blockIdx.x;
    const int t = threadIdx.x;
    const float4* src = reinterpret_cast<const float4*>(x + (size_t)m * K_DIM + t * 16);
    uint4 o = make_uint4(sign4_s8(src[0]), sign4_s8(src[1]),
                         sign4_s8(src[2]), sign4_s8(src[3]));
    *reinterpret_cast<uint4*>(g_A + (size_t)m * K_DIM + t * 16) = o;
}

__global__ void __launch_bounds__(256) pack_w_kernel(const float* __restrict__ w,
                                                     const float* __restrict__ th) {
    const int n = blockIdx.x;
    const int t = threadIdx.x;
    const float thr = th[n];
    const float4* src = reinterpret_cast<const float4*>(w + (size_t)n * K_DIM + t * 16);
    float4 v0 = src[0], v1 = src[1], v2 = src[2], v3 = src[3];
    v0.x -= thr; v0.y -= thr; v0.z -= thr; v0.w -= thr;
    v1.x -= thr; v1.y -= thr; v1.z -= thr; v1.w -= thr;
    v2.x -= thr; v2.y -= thr; v2.z -= thr; v2.w -= thr;
    v3.x -= thr; v3.y -= thr; v3.z -= thr; v3.w -= thr;
    uint4 o = make_uint4(sign4_s8(v0), sign4_s8(v1), sign4_s8(v2), sign4_s8(v3));
    *reinterpret_cast<uint4*>(g_B + (size_t)n * K_DIM + t * 16) = o;
}

// ---------------------------------------------------------------------------
// GEMM helpers
// ---------------------------------------------------------------------------
__device__ __forceinline__ uint32_t smem_u32(const void* p) {
    uint32_t a;
    asm("{ .reg .u64 t; cvta.to.shared.u64 t, %1; cvt.u32.u64 %0, t; }"
        : "=r"(a) : "l"(p));
    return a;
}

__device__ __forceinline__ void cp_async16(uint32_t dst, const void* src) {
    asm volatile("cp.async.cg.shared.global [%0], [%1], 16;"
                 :: "r"(dst), "l"(src) : "memory");
}
__device__ __forceinline__ void cp_commit() {
    asm volatile("cp.async.commit_group;" ::: "memory");
}
template <int N>
__device__ __forceinline__ void cp_wait() {
    asm volatile("cp.async.wait_group %0;" :: "n"(N) : "memory");
}

__device__ __forceinline__ void ldsm_x4(uint32_t a[4], uint32_t addr) {
    asm volatile("ldmatrix.sync.aligned.m8n8.x4.shared.b16 {%0,%1,%2,%3}, [%4];"
                 : "=r"(a[0]), "=r"(a[1]), "=r"(a[2]), "=r"(a[3]) : "r"(addr));
}
__device__ __forceinline__ void ldsm_x2(uint32_t b[2], uint32_t addr) {
    asm volatile("ldmatrix.sync.aligned.m8n8.x2.shared.b16 {%0,%1}, [%2];"
                 : "=r"(b[0]), "=r"(b[1]) : "r"(addr));
}

__device__ __forceinline__ void imma(int c[4], const uint32_t a[4], const uint32_t b[2]) {
    asm volatile(
        "mma.sync.aligned.m16n8k32.row.col.s32.s8.s8.s32 "
        "{%0,%1,%2,%3}, {%4,%5,%6,%7}, {%8,%9}, {%0,%1,%2,%3};"
        : "+r"(c[0]), "+r"(c[1]), "+r"(c[2]), "+r"(c[3])
        : "r"(a[0]), "r"(a[1]), "r"(a[2]), "r"(a[3]), "r"(b[0]), "r"(b[1]));
}

// Swizzle: row has 4 x 16B chunks; chunk' = chunk ^ ((row>>1)&3).
// Rows 0..7 (64B apart) then map to 8 distinct 16B positions in the 128B
// bank space -> conflict-free ldmatrix and cp.async stores.
__device__ __forceinline__ uint32_t swz(int row, int chunk) {
    return (uint32_t)(row * 64 + ((chunk ^ ((row >> 1) & 3)) << 4));
}

// ---------------------------------------------------------------------------
// GEMM kernel: 256 threads, warp grid 2(m) x 4(n), warp tile 64x64.
// ---------------------------------------------------------------------------
__global__ void __launch_bounds__(256, 1)
bgemm_kernel(const float* __restrict__ shift, float* __restrict__ out) {
    extern __shared__ char smem[];
    const uint32_t sb = smem_u32(smem);

    const int tid  = threadIdx.x;
    const int wid  = tid >> 5;
    const int lane = tid & 31;
    const int wm = (wid >> 2) * 64;       // warp m offset in CTA tile
    const int wn = (wid & 3) * 64;        // warp n offset
    const int m0 = blockIdx.y * BM;
    const int n0 = blockIdx.x * BN;

    const signed char* baseA = g_A + (size_t)m0 * K_DIM;
    const signed char* baseB = g_B + (size_t)n0 * K_DIM;

    int acc[4][8][4];
#pragma unroll
    for (int i = 0; i < 4; i++)
#pragma unroll
        for (int j = 0; j < 8; j++)
#pragma unroll
            for (int r = 0; r < 4; r++) acc[i][j][r] = 0;

    // ---- cp.async stage loader (each thread: 2 A chunks + 4 B chunks) ----
    auto load_stage = [&](int kc, int slot) {
        const uint32_t sA = sb + slot * ST;
        const uint32_t sB = sA + A_ST;
        const size_t kb = (size_t)kc * BK;
#pragma unroll
        for (int q = 0; q < 2; q++) {
            int chunk = tid + 256 * q;          // 0..511
            int row = chunk >> 2, c = chunk & 3;
            cp_async16(sA + swz(row, c), baseA + (size_t)row * K_DIM + kb + c * 16);
        }
#pragma unroll
        for (int q = 0; q < 4; q++) {
            int chunk = tid + 256 * q;          // 0..1023
            int row = chunk >> 2, c = chunk & 3;
            cp_async16(sB + swz(row, c), baseB + (size_t)row * K_DIM + kb + c * 16);
        }
        cp_commit();
    };

    // ---- ldmatrix per-lane address components ----
    // A (x4): matrices M0..M3 = (rows0-7,k0-15)(rows8-15,k0-15)(rows0-7,k16-31)(rows8-15,k16-31)
    const int a_row_in16 = ((lane >> 3) & 1) * 8 + (lane & 7);  // row within m16
    const int a_kbit     = (lane >> 4) & 1;                     // 16B-chunk within k32
    // B (x2): matrices (n0-7,k0-15)(n0-7,k16-31); lanes>=16 mirror 0..15
    const int b_n_in8 = lane & 7;
    const int b_kbit  = (lane >> 3) & 1;

    // ---- pipeline prologue ----
    for (int s = 0; s < STAGES - 1; s++) load_stage(s, s);

    for (int kc = 0; kc < NKC; kc++) {
        cp_wait<STAGES - 2>();
        __syncthreads();
        if (kc + STAGES - 1 < NKC) load_stage(kc + STAGES - 1, (kc + STAGES - 1) & (STAGES - 1));

        const uint32_t sA = sb + (kc & (STAGES - 1)) * ST;
        const uint32_t sB = sA + A_ST;

#pragma unroll
        for (int h = 0; h < 2; h++) {           // two k32 halves of the 64B chunk
            uint32_t af[4][4];
#pragma unroll
            for (int i = 0; i < 4; i++) {
                const int row = wm + i * 16 + a_row_in16;
                ldsm_x4(af[i], sA + swz(row, h * 2 + a_kbit));
            }
            uint32_t bf[8][2];
#pragma unroll
            for (int j = 0; j < 8; j++) {
                const int nrow = wn + j * 8 + b_n_in8;
                ldsm_x2(bf[j], sB + swz(nrow, h * 2 + b_kbit));
            }
#pragma unroll
            for (int i = 0; i < 4; i++)
#pragma unroll
                for (int j = 0; j < 8; j++)
                    imma(acc[i][j], af[i], bf[j]);
        }
    }

    // ---- epilogue ----
    const float sp = *shift;
    const float scale = exp2f(rintf(fminf(fmaxf(sp, -8.0f), 0.0f)));

    const int er = lane >> 2;            // 0..7
    const int ec = (lane & 3) * 2;       // 0,2,4,6
#pragma unroll
    for (int i = 0; i < 4; i++) {
        const size_t row0 = (size_t)(m0 + wm + i * 16 + er);
        float* p0 = out + row0 * N_DIM + n0 + wn + ec;
        float* p1 = out + (row0 + 8) * N_DIM + n0 + wn + ec;
#pragma unroll
        for (int j = 0; j < 8; j++) {
            float2 v0, v1;
            v0.x = scale * (float)acc[i][j][0];
            v0.y = scale * (float)acc[i][j][1];
            v1.x = scale * (float)acc[i][j][2];
            v1.y = scale * (float)acc[i][j][3];
            *reinterpret_cast<float2*>(p0 + j * 8) = v0;
            *reinterpret_cast<float2*>(p1 + j * 8) = v1;
        }
    }
}

// ---------------------------------------------------------------------------
// Launch
// ---------------------------------------------------------------------------
extern "C" void kernel_launch(void* const* d_in, const int* in_sizes, int n_in,
                              void* d_out, int out_size) {
    const float* x     = (const float*)d_in[0];
    const float* w     = (const float*)d_in[1];
    const float* th    = (const float*)d_in[2];
    const float* shift = (const float*)d_in[3];
    float* out = (float*)d_out;

    pack_x_kernel<<<M_DIM, 256>>>(x);
    pack_w_kernel<<<N_DIM, 256>>>(w, th);

    cudaFuncSetAttribute(bgemm_kernel, cudaFuncAttributeMaxDynamicSharedMemorySize, SMEM_TOTAL);
    dim3 grid(N_DIM / BN, M_DIM / BM);   // (64, 64)
    bgemm_kernel<<<grid, 256, SMEM_TOTAL>>>(shift, out);

    (void)in_sizes; (void)n_in; (void)out_size;
}

// round 7
// speedup vs baseline: 1.0564x; 1.0564x over previous
#include <cuda_runtime.h>
#include <cstdint>

// ---------------------------------------------------------------------------
// out = scale * signGEMM,  scale = 2^rint(clip(shift,-8,0))
// x [4,2048,4096] -> M=8192, K=4096 ; weight [16384,4096] -> N=16384
// Signs packed as int8 +/-1; IMMA (mma.sync m16n8k32 s8.s8.s32) is exact.
// Round-5 diagnostic: 64x32 warp tile (64 acc regs), 2 CTAs/SM.
// ---------------------------------------------------------------------------
constexpr int K_DIM = 4096;
constexpr int M_DIM = 8192;
constexpr int N_DIM = 16384;

constexpr int BM = 128;
constexpr int BN = 128;
constexpr int BK = 64;                  // int8 K-elems per chunk
constexpr int NKC = K_DIM / BK;         // 64
constexpr int STAGES = 4;
constexpr int A_ST = BM * BK;           // 8192
constexpr int B_ST = BN * BK;           // 8192
constexpr int ST   = A_ST + B_ST;       // 16384
constexpr int SMEM_TOTAL = STAGES * ST; // 65536

__device__ __align__(1024) signed char g_A[(size_t)M_DIM * K_DIM]; // 32 MB
__device__ __align__(1024) signed char g_B[(size_t)N_DIM * K_DIM]; // 64 MB

// ---------------------------------------------------------------------------
// Pack kernels: sign -> int8 +/-1, row-major.
// ---------------------------------------------------------------------------
__device__ __forceinline__ uint32_t sign4_s8(float4 v) {
    uint32_t w;
    w  = (v.x >= 0.0f ? 0x01u : 0xFFu);
    w |= (v.y >= 0.0f ? 0x01u : 0xFFu) << 8;
    w |= (v.z >= 0.0f ? 0x01u : 0xFFu) << 16;
    w |= (v.w >= 0.0f ? 0x01u : 0xFFu) << 24;
    return w;
}

__global__ void __launch_bounds__(256) pack_x_kernel(const float* __restrict__ x) {
    const int m = blockIdx.x;
    const int t = threadIdx.x;
    const float4* src = reinterpret_cast<const float4*>(x + (size_t)m * K_DIM + t * 16);
    uint4 o = make_uint4(sign4_s8(src[0]), sign4_s8(src[1]),
                         sign4_s8(src[2]), sign4_s8(src[3]));
    *reinterpret_cast<uint4*>(g_A + (size_t)m * K_DIM + t * 16) = o;
}

__global__ void __launch_bounds__(256) pack_w_kernel(const float* __restrict__ w,
                                                     const float* __restrict__ th) {
    const int n = blockIdx.x;
    const int t = threadIdx.x;
    const float thr = th[n];
    const float4* src = reinterpret_cast<const float4*>(w + (size_t)n * K_DIM + t * 16);
    float4 v0 = src[0], v1 = src[1], v2 = src[2], v3 = src[3];
    v0.x -= thr; v0.y -= thr; v0.z -= thr; v0.w -= thr;
    v1.x -= thr; v1.y -= thr; v1.z -= thr; v1.w -= thr;
    v2.x -= thr; v2.y -= thr; v2.z -= thr; v2.w -= thr;
    v3.x -= thr; v3.y -= thr; v3.z -= thr; v3.w -= thr;
    uint4 o = make_uint4(sign4_s8(v0), sign4_s8(v1), sign4_s8(v2), sign4_s8(v3));
    *reinterpret_cast<uint4*>(g_B + (size_t)n * K_DIM + t * 16) = o;
}

// ---------------------------------------------------------------------------
// GEMM helpers
// ---------------------------------------------------------------------------
__device__ __forceinline__ uint32_t smem_u32(const void* p) {
    uint32_t a;
    asm("{ .reg .u64 t; cvta.to.shared.u64 t, %1; cvt.u32.u64 %0, t; }"
        : "=r"(a) : "l"(p));
    return a;
}

__device__ __forceinline__ void cp_async16(uint32_t dst, const void* src) {
    asm volatile("cp.async.cg.shared.global [%0], [%1], 16;"
                 :: "r"(dst), "l"(src) : "memory");
}
__device__ __forceinline__ void cp_commit() {
    asm volatile("cp.async.commit_group;" ::: "memory");
}
template <int N>
__device__ __forceinline__ void cp_wait() {
    asm volatile("cp.async.wait_group %0;" :: "n"(N) : "memory");
}

__device__ __forceinline__ void ldsm_x4(uint32_t a[4], uint32_t addr) {
    asm volatile("ldmatrix.sync.aligned.m8n8.x4.shared.b16 {%0,%1,%2,%3}, [%4];"
                 : "=r"(a[0]), "=r"(a[1]), "=r"(a[2]), "=r"(a[3]) : "r"(addr));
}
__device__ __forceinline__ void ldsm_x2(uint32_t b[2], uint32_t addr) {
    asm volatile("ldmatrix.sync.aligned.m8n8.x2.shared.b16 {%0,%1}, [%2];"
                 : "=r"(b[0]), "=r"(b[1]) : "r"(addr));
}

__device__ __forceinline__ void imma(int c[4], const uint32_t a[4], const uint32_t b[2]) {
    asm volatile(
        "mma.sync.aligned.m16n8k32.row.col.s32.s8.s8.s32 "
        "{%0,%1,%2,%3}, {%4,%5,%6,%7}, {%8,%9}, {%0,%1,%2,%3};"
        : "+r"(c[0]), "+r"(c[1]), "+r"(c[2]), "+r"(c[3])
        : "r"(a[0]), "r"(a[1]), "r"(a[2]), "r"(a[3]), "r"(b[0]), "r"(b[1]));
}

// Swizzle: row of 64B has 4 x 16B chunks; chunk' = chunk ^ ((row>>1)&3).
// 8 consecutive rows map to 8 distinct 16B granules in the 128B bank space
// -> conflict-free ldmatrix and cp.async stores (verified, rel_err 0).
__device__ __forceinline__ uint32_t swz(int row, int chunk) {
    return (uint32_t)(row * 64 + ((chunk ^ ((row >> 1) & 3)) << 4));
}

// ---------------------------------------------------------------------------
// GEMM kernel: 256 threads, warp grid 2(m) x 4(n), warp tile 64x32,
// 2 CTAs/SM (launch_bounds caps regs at 128).
// ---------------------------------------------------------------------------
__global__ void __launch_bounds__(256, 2)
bgemm_kernel(const float* __restrict__ shift, float* __restrict__ out) {
    extern __shared__ char smem[];
    const uint32_t sb = smem_u32(smem);

    const int tid  = threadIdx.x;
    const int wid  = tid >> 5;
    const int lane = tid & 31;
    const int wm = (wid >> 2) * 64;       // 0 or 64
    const int wn = (wid & 3) * 32;        // 0,32,64,96
    const int m0 = blockIdx.y * BM;
    const int n0 = blockIdx.x * BN;

    const signed char* baseA = g_A + (size_t)m0 * K_DIM;
    const signed char* baseB = g_B + (size_t)n0 * K_DIM;

    int acc[4][4][4];                     // [i: m16][j: n8][frag] = 64 regs
#pragma unroll
    for (int i = 0; i < 4; i++)
#pragma unroll
        for (int j = 0; j < 4; j++)
#pragma unroll
            for (int r = 0; r < 4; r++) acc[i][j][r] = 0;

    // ---- cp.async stage loader: 1024 16B-chunks / 256 threads = 4 each ----
    const int l_row = tid >> 2;          // 0..63
    const int l_c   = tid & 3;           // 0..3
    auto load_stage = [&](int kc, int slot) {
        const uint32_t sA = sb + slot * ST;
        const uint32_t sB = sA + A_ST;
        const size_t kb = (size_t)kc * BK;
#pragma unroll
        for (int q = 0; q < 2; q++) {
            const int row = l_row + q * 64;
            cp_async16(sA + swz(row, l_c), baseA + (size_t)row * K_DIM + kb + l_c * 16);
            cp_async16(sB + swz(row, l_c), baseB + (size_t)row * K_DIM + kb + l_c * 16);
        }
        cp_commit();
    };

    // ---- ldmatrix per-lane address components (same verified layout) ----
    const int a_row_in16 = ((lane >> 3) & 1) * 8 + (lane & 7);
    const int a_kbit     = (lane >> 4) & 1;
    const int b_n_in8 = lane & 7;
    const int b_kbit  = (lane >> 3) & 1;

    for (int s = 0; s < STAGES - 1; s++) load_stage(s, s);

    for (int kc = 0; kc < NKC; kc++) {
        cp_wait<STAGES - 2>();
        __syncthreads();
        if (kc + STAGES - 1 < NKC)
            load_stage(kc + STAGES - 1, (kc + STAGES - 1) & (STAGES - 1));

        const uint32_t sA = sb + (kc & (STAGES - 1)) * ST;
        const uint32_t sB = sA + A_ST;

#pragma unroll
        for (int h = 0; h < 2; h++) {           // two k32 halves per 64B chunk
            uint32_t af[4][4];
#pragma unroll
            for (int i = 0; i < 4; i++)
                ldsm_x4(af[i], sA + swz(wm + i * 16 + a_row_in16, h * 2 + a_kbit));
            uint32_t bf[4][2];
#pragma unroll
            for (int j = 0; j < 4; j++)
                ldsm_x2(bf[j], sB + swz(wn + j * 8 + b_n_in8, h * 2 + b_kbit));
#pragma unroll
            for (int i = 0; i < 4; i++)
#pragma unroll
                for (int j = 0; j < 4; j++)
                    imma(acc[i][j], af[i], bf[j]);
        }
    }

    // ---- epilogue ----
    const float sp = *shift;
    const float scale = exp2f(rintf(fminf(fmaxf(sp, -8.0f), 0.0f)));

    const int er = lane >> 2;            // 0..7
    const int ec = (lane & 3) * 2;       // 0,2,4,6
#pragma unroll
    for (int i = 0; i < 4; i++) {
        const size_t row0 = (size_t)(m0 + wm + i * 16 + er);
        float* p0 = out + row0 * N_DIM + n0 + wn + ec;
        float* p1 = out + (row0 + 8) * N_DIM + n0 + wn + ec;
#pragma unroll
        for (int j = 0; j < 4; j++) {
            float2 v0, v1;
            v0.x = scale * (float)acc[i][j][0];
            v0.y = scale * (float)acc[i][j][1];
            v1.x = scale * (float)acc[i][j][2];
            v1.y = scale * (float)acc[i][j][3];
            *reinterpret_cast<float2*>(p0 + j * 8) = v0;
            *reinterpret_cast<float2*>(p1 + j * 8) = v1;
        }
    }
}

// ---------------------------------------------------------------------------
// Launch
// ---------------------------------------------------------------------------
extern "C" void kernel_launch(void* const* d_in, const int* in_sizes, int n_in,
                              void* d_out, int out_size) {
    const float* x     = (const float*)d_in[0];
    const float* w     = (const float*)d_in[1];
    const float* th    = (const float*)d_in[2];
    const float* shift = (const float*)d_in[3];
    float* out = (float*)d_out;

    pack_x_kernel<<<M_DIM, 256>>>(x);
    pack_w_kernel<<<N_DIM, 256>>>(w, th);

    cudaFuncSetAttribute(bgemm_kernel, cudaFuncAttributeMaxDynamicSharedMemorySize, SMEM_TOTAL);
    dim3 grid(N_DIM / BN, M_DIM / BM);   // (128, 64)
    bgemm_kernel<<<grid, 256, SMEM_TOTAL>>>(shift, out);

    (void)in_sizes; (void)n_in; (void)out_size;
}

// round 8
// speedup vs baseline: 1.8267x; 1.7291x over previous
#include <cuda_runtime.h>
#include <cstdint>

// ---------------------------------------------------------------------------
// out = scale * (K - 2*mismatch), scale = 2^rint(clip(shift,-8,0))
// x [4,2048,4096] -> M=8192, K=4096 ; weight [16384,4096] -> N=16384
// Bitboard popcount GEMM with Harley-Seal CSA trees: POPC (quarter-rate unit)
// traded for LOP3 (full-rate alu pipe). Exact integer math -> rel_err 0.
// ---------------------------------------------------------------------------
constexpr int K_DIM = 4096;
constexpr int KW    = K_DIM / 32;      // 128 words/row
constexpr int M_DIM = 8192;
constexpr int N_DIM = 16384;

constexpr int BM = 64;
constexpr int BN = 128;
constexpr int BKW = 32;                // words per stage chunk (128B of K)
constexpr int NKI = KW / BKW;          // 4 outer iterations
constexpr int ROW_B = 144;             // smem row stride bytes (32w=128B + 16 pad)
constexpr int A_ST = BM * ROW_B;       // 9216
constexpr int B_ST = BN * ROW_B;       // 18432
constexpr int ST   = A_ST + B_ST;      // 27648
constexpr int SMEM_TOTAL = 2 * ST;     // 55296 (double buffered)

__device__ __align__(16) uint32_t g_Aw[(size_t)M_DIM * KW];  // 4 MB
__device__ __align__(16) uint32_t g_Bw[(size_t)N_DIM * KW];  // 8 MB

// ---------------------------------------------------------------------------
// Pack: one thread builds one 32-bit sign word from 32 consecutive floats.
// bit l of word wi = (elem[wi*32+l] >= 0).  (>=0 matches jnp.where(x>=0,...))
// ---------------------------------------------------------------------------
__global__ void __launch_bounds__(256) pack_x_kernel(const float* __restrict__ x) {
    const size_t idx = (size_t)blockIdx.x * 256 + threadIdx.x;     // word index
    const float4* s = reinterpret_cast<const float4*>(x + (idx << 5));
    uint32_t w = 0;
#pragma unroll
    for (int q = 0; q < 8; q++) {
        float4 v = s[q];
        w |= (uint32_t)(v.x >= 0.0f) << (q * 4 + 0);
        w |= (uint32_t)(v.y >= 0.0f) << (q * 4 + 1);
        w |= (uint32_t)(v.z >= 0.0f) << (q * 4 + 2);
        w |= (uint32_t)(v.w >= 0.0f) << (q * 4 + 3);
    }
    g_Aw[idx] = w;
}

__global__ void __launch_bounds__(256) pack_w_kernel(const float* __restrict__ wgt,
                                                     const float* __restrict__ th) {
    const size_t idx = (size_t)blockIdx.x * 256 + threadIdx.x;
    const float thr = th[idx >> 7];                 // row = idx / KW
    const float4* s = reinterpret_cast<const float4*>(wgt + (idx << 5));
    uint32_t w = 0;
#pragma unroll
    for (int q = 0; q < 8; q++) {
        float4 v = s[q];
        w |= (uint32_t)(v.x - thr >= 0.0f) << (q * 4 + 0);
        w |= (uint32_t)(v.y - thr >= 0.0f) << (q * 4 + 1);
        w |= (uint32_t)(v.z - thr >= 0.0f) << (q * 4 + 2);
        w |= (uint32_t)(v.w - thr >= 0.0f) << (q * 4 + 3);
    }
    g_Bw[idx] = w;
}

// ---------------------------------------------------------------------------
// helpers
// ---------------------------------------------------------------------------
__device__ __forceinline__ uint32_t smem_u32(const void* p) {
    uint32_t a;
    asm("{ .reg .u64 t; cvta.to.shared.u64 t, %1; cvt.u32.u64 %0, t; }"
        : "=r"(a) : "l"(p));
    return a;
}
__device__ __forceinline__ void cp_async16(uint32_t dst, const void* src) {
    asm volatile("cp.async.ca.shared.global [%0], [%1], 16;"
                 :: "r"(dst), "l"(src) : "memory");
}
__device__ __forceinline__ void cp_commit() {
    asm volatile("cp.async.commit_group;" ::: "memory");
}
template <int N>
__device__ __forceinline__ void cp_wait() {
    asm volatile("cp.async.wait_group %0;" :: "n"(N) : "memory");
}
__device__ __forceinline__ uint32_t maj3(uint32_t a, uint32_t b, uint32_t c) {
    return (a & b) | (a & c) | (b & c);              // one LOP3 0xE8
}

// 8-word xor + carry-save adder tree: 8 XOR + 14 LOP3 + 4 POPC + 4 IMAD
// counts sum of set bits of (a[w]^b[w]) for w=0..7 into acc.
__device__ __forceinline__ void tree8(const uint32_t a[8], const uint32_t b[8],
                                      int& acc) {
    uint32_t x0 = a[0] ^ b[0], x1 = a[1] ^ b[1], x2 = a[2] ^ b[2], x3 = a[3] ^ b[3];
    uint32_t x4 = a[4] ^ b[4], x5 = a[5] ^ b[5], x6 = a[6] ^ b[6], x7 = a[7] ^ b[7];
    uint32_t sa = x0 ^ x1 ^ x2,  ca = maj3(x0, x1, x2);
    uint32_t sb = x3 ^ x4 ^ x5,  cb = maj3(x3, x4, x5);
    uint32_t sc = x6 ^ x7,       cc = x6 & x7;
    uint32_t S1 = sa ^ sb ^ sc,  C1 = maj3(sa, sb, sc);   // w1, w2
    uint32_t S2 = ca ^ cb ^ cc,  C2 = maj3(ca, cb, cc);   // w2, w4
    uint32_t T2 = C1 ^ S2,       T4 = C1 & S2;            // w2, w4
    uint32_t F4 = C2 ^ T4,       E8 = C2 & T4;            // w4, w8
    acc += __popc(S1);
    acc += __popc(T2) * 2;
    acc += __popc(F4) * 4;
    acc += __popc(E8) * 8;
}

// ---------------------------------------------------------------------------
// GEMM: CTA tile 64(m) x 128(n), 256 threads = 32(tx,n) x 8(ty,m),
// thread tile 8m x 4n. B smem stored j-major: smem row = j*32+tx so the
// 32 lanes of a bv load stride 144B (== 16 mod 128) -> conflict-free LDS.128.
// av loads are warp-uniform (same ty) -> broadcast.
// ---------------------------------------------------------------------------
__global__ void __launch_bounds__(256, 2)
bgemm_kernel(const float* __restrict__ shift, float* __restrict__ out) {
    extern __shared__ char smem[];
    const uint32_t sbase = smem_u32(smem);

    const int tid = threadIdx.x;
    const int tx = tid & 31;          // n group
    const int ty = tid >> 5;          // m group == warp id
    const int m0 = blockIdx.y * BM;
    const int n0 = blockIdx.x * BN;

    int acc[8][4];
#pragma unroll
    for (int i = 0; i < 8; i++)
#pragma unroll
        for (int j = 0; j < 4; j++) acc[i][j] = 0;

    // stage loader: 512 A-chunks + 1024 B-chunks of 16B, 6 per thread
    auto load_stage = [&](int kk, int s) {
        const uint32_t sA = sbase + s * ST;
        const uint32_t sB = sA + A_ST;
        const int kw0 = kk * BKW;
#pragma unroll
        for (int q = 0; q < 6; q++) {
            const int c = tid + 256 * q;
            if (c < 512) {
                const int row = c >> 3, ci = c & 7;
                cp_async16(sA + row * ROW_B + ci * 16,
                           reinterpret_cast<const char*>(
                               g_Aw + (size_t)(m0 + row) * KW + kw0) + ci * 16);
            } else {
                const int bchunk = c - 512;
                const int rs = bchunk >> 3, ci = bchunk & 7;
                const int j = rs >> 5, t2 = rs & 31;
                const int gn = n0 + t2 * 4 + j;
                cp_async16(sB + rs * ROW_B + ci * 16,
                           reinterpret_cast<const char*>(
                               g_Bw + (size_t)gn * KW + kw0) + ci * 16);
            }
        }
        cp_commit();
    };

    auto compute = [&](int s) {
        const char* cA = smem + s * ST;
        const char* cB = cA + A_ST;
#pragma unroll
        for (int sub = 0; sub < 4; sub++) {          // 4 x 8-word sub-chunks
            uint32_t bv[4][8];
#pragma unroll
            for (int j = 0; j < 4; j++) {
                const char* p = cB + (j * 32 + tx) * ROW_B + sub * 32;
                uint4 lo = *reinterpret_cast<const uint4*>(p);
                uint4 hi = *reinterpret_cast<const uint4*>(p + 16);
                bv[j][0] = lo.x; bv[j][1] = lo.y; bv[j][2] = lo.z; bv[j][3] = lo.w;
                bv[j][4] = hi.x; bv[j][5] = hi.y; bv[j][6] = hi.z; bv[j][7] = hi.w;
            }
#pragma unroll
            for (int i = 0; i < 8; i++) {
                const char* p = cA + (ty * 8 + i) * ROW_B + sub * 32;
                uint4 lo = *reinterpret_cast<const uint4*>(p);
                uint4 hi = *reinterpret_cast<const uint4*>(p + 16);
                uint32_t av[8] = {lo.x, lo.y, lo.z, lo.w, hi.x, hi.y, hi.z, hi.w};
#pragma unroll
                for (int j = 0; j < 4; j++) tree8(av, bv[j], acc[i][j]);
            }
        }
    };

    load_stage(0, 0);
#pragma unroll
    for (int kk = 0; kk < NKI; kk++) {
        if (kk + 1 < NKI) {
            load_stage(kk + 1, (kk + 1) & 1);
            cp_wait<1>();
        } else {
            cp_wait<0>();
        }
        __syncthreads();
        compute(kk & 1);
        __syncthreads();
    }

    const float sp = *shift;
    const float scale = exp2f(rintf(fminf(fmaxf(sp, -8.0f), 0.0f)));

#pragma unroll
    for (int i = 0; i < 8; i++) {
        const size_t row = (size_t)(m0 + ty * 8 + i);
        float4 v;
        v.x = scale * (float)(K_DIM - 2 * acc[i][0]);
        v.y = scale * (float)(K_DIM - 2 * acc[i][1]);
        v.z = scale * (float)(K_DIM - 2 * acc[i][2]);
        v.w = scale * (float)(K_DIM - 2 * acc[i][3]);
        *reinterpret_cast<float4*>(out + row * N_DIM + n0 + tx * 4) = v;
    }
}

// ---------------------------------------------------------------------------
// Launch
// ---------------------------------------------------------------------------
extern "C" void kernel_launch(void* const* d_in, const int* in_sizes, int n_in,
                              void* d_out, int out_size) {
    const float* x     = (const float*)d_in[0];
    const float* w     = (const float*)d_in[1];
    const float* th    = (const float*)d_in[2];
    const float* shift = (const float*)d_in[3];
    float* out = (float*)d_out;

    pack_x_kernel<<<(M_DIM * KW) / 256, 256>>>(x);
    pack_w_kernel<<<(N_DIM * KW) / 256, 256>>>(w, th);

    cudaFuncSetAttribute(bgemm_kernel, cudaFuncAttributeMaxDynamicSharedMemorySize, SMEM_TOTAL);
    dim3 grid(N_DIM / BN, M_DIM / BM);   // (128, 128)
    bgemm_kernel<<<grid, 256, SMEM_TOTAL>>>(shift, out);

    (void)in_sizes; (void)n_in; (void)out_size;
}

// round 12
// speedup vs baseline: 2.1019x; 1.1506x over previous
#include <cuda_runtime.h>
#include <cstdint>

// ---------------------------------------------------------------------------
// out = scale * (K - 2*mismatch), scale = 2^rint(clip(shift,-8,0))
// x [4,2048,4096] -> M=8192, K=4096 ; weight [16384,4096] -> N=16384
// Bitboard popcount GEMM. POPC is full-rate alu on sm_103 -> minimize total
// alu instructions: XOR + POPC + paired IADD3 = 2.5 instr/word.
// ---------------------------------------------------------------------------
constexpr int K_DIM = 4096;
constexpr int KW    = K_DIM / 32;      // 128 words/row
constexpr int M_DIM = 8192;
constexpr int N_DIM = 16384;

constexpr int BM = 64;
constexpr int BN = 128;
constexpr int BKW = 32;                // words per stage chunk (128B of K)
constexpr int NKI = KW / BKW;          // 4 outer iterations
constexpr int ROW_B = 144;             // smem row stride bytes (128B + 16 pad)
constexpr int A_ST = BM * ROW_B;       // 9216
constexpr int B_ST = BN * ROW_B;       // 18432
constexpr int ST   = A_ST + B_ST;      // 27648
constexpr int SMEM_TOTAL = 2 * ST;     // 55296 (double buffered)

__device__ __align__(16) uint32_t g_Aw[(size_t)M_DIM * KW];  // 4 MB
__device__ __align__(16) uint32_t g_Bw[(size_t)N_DIM * KW];  // 8 MB

// ---------------------------------------------------------------------------
// Pack: one thread builds one 32-bit sign word from 32 consecutive floats.
// ---------------------------------------------------------------------------
__global__ void __launch_bounds__(256) pack_x_kernel(const float* __restrict__ x) {
    const size_t idx = (size_t)blockIdx.x * 256 + threadIdx.x;     // word index
    const float4* s = reinterpret_cast<const float4*>(x + (idx << 5));
    uint32_t w = 0;
#pragma unroll
    for (int q = 0; q < 8; q++) {
        float4 v = s[q];
        w |= (uint32_t)(v.x >= 0.0f) << (q * 4 + 0);
        w |= (uint32_t)(v.y >= 0.0f) << (q * 4 + 1);
        w |= (uint32_t)(v.z >= 0.0f) << (q * 4 + 2);
        w |= (uint32_t)(v.w >= 0.0f) << (q * 4 + 3);
    }
    g_Aw[idx] = w;
}

__global__ void __launch_bounds__(256) pack_w_kernel(const float* __restrict__ wgt,
                                                     const float* __restrict__ th) {
    const size_t idx = (size_t)blockIdx.x * 256 + threadIdx.x;
    const float thr = th[idx >> 7];                 // row = idx / KW
    const float4* s = reinterpret_cast<const float4*>(wgt + (idx << 5));
    uint32_t w = 0;
#pragma unroll
    for (int q = 0; q < 8; q++) {
        float4 v = s[q];
        w |= (uint32_t)(v.x - thr >= 0.0f) << (q * 4 + 0);
        w |= (uint32_t)(v.y - thr >= 0.0f) << (q * 4 + 1);
        w |= (uint32_t)(v.z - thr >= 0.0f) << (q * 4 + 2);
        w |= (uint32_t)(v.w - thr >= 0.0f) << (q * 4 + 3);
    }
    g_Bw[idx] = w;
}

// ---------------------------------------------------------------------------
// helpers
// ---------------------------------------------------------------------------
__device__ __forceinline__ uint32_t smem_u32(const void* p) {
    uint32_t a;
    asm("{ .reg .u64 t; cvta.to.shared.u64 t, %1; cvt.u32.u64 %0, t; }"
        : "=r"(a) : "l"(p));
    return a;
}
__device__ __forceinline__ void cp_async16(uint32_t dst, const void* src) {
    asm volatile("cp.async.ca.shared.global [%0], [%1], 16;"
                 :: "r"(dst), "l"(src) : "memory");
}
__device__ __forceinline__ void cp_commit() {
    asm volatile("cp.async.commit_group;" ::: "memory");
}
template <int N>
__device__ __forceinline__ void cp_wait() {
    asm volatile("cp.async.wait_group %0;" :: "n"(N) : "memory");
}

// 8-word xor+popc with paired accumulation: 8 XOR + 8 POPC + 4 IADD3.
// acc += p0+p1 compiles to one three-input add; ptxas alternates the add
// chain between IADD3 (alu) and IMAD (fma) pipes.
__device__ __forceinline__ void dot8(const uint32_t a[8], const uint32_t b[8],
                                     int& acc) {
    int p0 = __popc(a[0] ^ b[0]);
    int p1 = __popc(a[1] ^ b[1]);
    acc += p0 + p1;
    int p2 = __popc(a[2] ^ b[2]);
    int p3 = __popc(a[3] ^ b[3]);
    acc += p2 + p3;
    int p4 = __popc(a[4] ^ b[4]);
    int p5 = __popc(a[5] ^ b[5]);
    acc += p4 + p5;
    int p6 = __popc(a[6] ^ b[6]);
    int p7 = __popc(a[7] ^ b[7]);
    acc += p6 + p7;
}

// ---------------------------------------------------------------------------
// GEMM: CTA tile 64(m) x 128(n), 256 threads = 32(tx,n) x 8(ty,m),
// thread tile 8m x 4n. B smem j-major (row = j*32+tx): bv LDS.128 lanes
// stride 144B == 16 mod 128 -> conflict-free; av loads warp-uniform broadcast.
// (Layout verified rel_err=0 in round 8.)
// ---------------------------------------------------------------------------
__global__ void __launch_bounds__(256, 2)
bgemm_kernel(const float* __restrict__ shift, float* __restrict__ out) {
    extern __shared__ char smem[];
    const uint32_t sbase = smem_u32(smem);

    const int tid = threadIdx.x;
    const int tx = tid & 31;          // n group
    const int ty = tid >> 5;          // m group == warp id
    const int m0 = blockIdx.y * BM;
    const int n0 = blockIdx.x * BN;

    int acc[8][4];
#pragma unroll
    for (int i = 0; i < 8; i++)
#pragma unroll
        for (int j = 0; j < 4; j++) acc[i][j] = 0;

    // stage loader: 512 A-chunks + 1024 B-chunks of 16B, 6 per thread
    auto load_stage = [&](int kk, int s) {
        const uint32_t sA = sbase + s * ST;
        const uint32_t sB = sA + A_ST;
        const int kw0 = kk * BKW;
#pragma unroll
        for (int q = 0; q < 6; q++) {
            const int c = tid + 256 * q;
            if (c < 512) {
                const int row = c >> 3, ci = c & 7;
                cp_async16(sA + row * ROW_B + ci * 16,
                           reinterpret_cast<const char*>(
                               g_Aw + (size_t)(m0 + row) * KW + kw0) + ci * 16);
            } else {
                const int bchunk = c - 512;
                const int rs = bchunk >> 3, ci = bchunk & 7;
                const int j = rs >> 5, t2 = rs & 31;
                const int gn = n0 + t2 * 4 + j;
                cp_async16(sB + rs * ROW_B + ci * 16,
                           reinterpret_cast<const char*>(
                               g_Bw + (size_t)gn * KW + kw0) + ci * 16);
            }
        }
        cp_commit();
    };

    auto compute = [&](int s) {
        const char* cA = smem + s * ST;
        const char* cB = cA + A_ST;
#pragma unroll
        for (int sub = 0; sub < 4; sub++) {          // 4 x 8-word sub-chunks
            uint32_t bv[4][8];
#pragma unroll
            for (int j = 0; j < 4; j++) {
                const char* p = cB + (j * 32 + tx) * ROW_B + sub * 32;
                uint4 lo = *reinterpret_cast<const uint4*>(p);
                uint4 hi = *reinterpret_cast<const uint4*>(p + 16);
                bv[j][0] = lo.x; bv[j][1] = lo.y; bv[j][2] = lo.z; bv[j][3] = lo.w;
                bv[j][4] = hi.x; bv[j][5] = hi.y; bv[j][6] = hi.z; bv[j][7] = hi.w;
            }
#pragma unroll
            for (int i = 0; i < 8; i++) {
                const char* p = cA + (ty * 8 + i) * ROW_B + sub * 32;
                uint4 lo = *reinterpret_cast<const uint4*>(p);
                uint4 hi = *reinterpret_cast<const uint4*>(p + 16);
                uint32_t av[8] = {lo.x, lo.y, lo.z, lo.w, hi.x, hi.y, hi.z, hi.w};
#pragma unroll
                for (int j = 0; j < 4; j++) dot8(av, bv[j], acc[i][j]);
            }
        }
    };

    load_stage(0, 0);
#pragma unroll
    for (int kk = 0; kk < NKI; kk++) {
        if (kk + 1 < NKI) {
            load_stage(kk + 1, (kk + 1) & 1);
            cp_wait<1>();
        } else {
            cp_wait<0>();
        }
        __syncthreads();
        compute(kk & 1);
        __syncthreads();
    }

    const float sp = *shift;
    const float scale = exp2f(rintf(fminf(fmaxf(sp, -8.0f), 0.0f)));

#pragma unroll
    for (int i = 0; i < 8; i++) {
        const size_t row = (size_t)(m0 + ty * 8 + i);
        float4 v;
        v.x = scale * (float)(K_DIM - 2 * acc[i][0]);
        v.y = scale * (float)(K_DIM - 2 * acc[i][1]);
        v.z = scale * (float)(K_DIM - 2 * acc[i][2]);
        v.w = scale * (float)(K_DIM - 2 * acc[i][3]);
        *reinterpret_cast<float4*>(out + row * N_DIM + n0 + tx * 4) = v;
    }
}

// ---------------------------------------------------------------------------
// Launch
// ---------------------------------------------------------------------------
extern "C" void kernel_launch(void* const* d_in, const int* in_sizes, int n_in,
                              void* d_out, int out_size) {
    const float* x     = (const float*)d_in[0];
    const float* w     = (const float*)d_in[1];
    const float* th    = (const float*)d_in[2];
    const float* shift = (const float*)d_in[3];
    float* out = (float*)d_out;

    pack_x_kernel<<<(M_DIM * KW) / 256, 256>>>(x);
    pack_w_kernel<<<(N_DIM * KW) / 256, 256>>>(w, th);

    cudaFuncSetAttribute(bgemm_kernel, cudaFuncAttributeMaxDynamicSharedMemorySize, SMEM_TOTAL);
    dim3 grid(N_DIM / BN, M_DIM / BM);   // (128, 128)
    bgemm_kernel<<<grid, 256, SMEM_TOTAL>>>(shift, out);

    (void)in_sizes; (void)n_in; (void)out_size;
}